// round 4
// baseline (speedup 1.0000x reference)
#include <cuda_runtime.h>
#include <cuda_bf16.h>
#include <cstdint>

#define NROWS 8192
#define DDIM  512
#define BM    128
#define BK    32
#define NT    256
#define NBLK  (NROWS/BM)               /* 64   */
#define NTRI  (NBLK*(NBLK+1)/2)        /* 2080 */
#define SST   40                       /* smem row stride (elems): conflict-free + 16B-aligned */
#define LMARGIN 0.5f
#define FBIG  3.402823466e+38f

// ---------------- scratch (static device globals; no allocation) -------------
__device__ __nv_bfloat16 g_l2h[NROWS*DDIM];   // normalized rows, bf16 (8 MB, L2-resident)
__device__ unsigned      g_minpos[NROWS];     // ordered-uint min of same-class sim
__device__ unsigned      g_maxneg[NROWS];     // ordered-uint max of diff-class sim
__device__ int           g_tgt[NROWS];

// Monotonic float<->uint mapping: atomicMin/Max on unsigned == float min/max.
__device__ __forceinline__ unsigned ordu(float f) {
    unsigned u = __float_as_uint(f);
    return (u & 0x80000000u) ? ~u : (u | 0x80000000u);
}
__device__ __forceinline__ float deordu(unsigned u) {
    return (u & 0x80000000u) ? __uint_as_float(u & 0x7fffffffu)
                             : __uint_as_float(~u);
}

// ---------------- kernel 1: L2-normalize -> bf16, init, target convert -------
__global__ void k_normalize(const float* __restrict__ x, const int* __restrict__ t32)
{
    int row = blockIdx.x;
    int tid = threadIdx.x;
    __shared__ float sred[4];
    __shared__ float sinv;
    __shared__ int   sis64;

    const float4* xr = (const float4*)(x + (size_t)row * DDIM);
    float4 v = xr[tid];
    float ss = v.x*v.x + v.y*v.y + v.z*v.z + v.w*v.w;
    #pragma unroll
    for (int o = 16; o > 0; o >>= 1) ss += __shfl_xor_sync(0xffffffffu, ss, o);
    if ((tid & 31) == 0) sred[tid >> 5] = ss;

    // int64 vs int32 target detection: int64 values <512 => every odd word is 0.
    if (tid < 32) {
        int hv = t32[2*tid + 1];
        unsigned bal = __ballot_sync(0xffffffffu, hv == 0);
        if (tid == 0) sis64 = (bal == 0xffffffffu);
    }
    __syncthreads();
    if (tid == 0) {
        sinv = rsqrtf(sred[0] + sred[1] + sred[2] + sred[3]);
        g_minpos[row] = ordu(FBIG);
        g_maxneg[row] = ordu(-FBIG);
        g_tgt[row]    = sis64 ? t32[2*row] : t32[row];
    }
    __syncthreads();
    float inv = sinv;
    __nv_bfloat16 h0 = __float2bfloat16(v.x*inv);
    __nv_bfloat16 h1 = __float2bfloat16(v.y*inv);
    __nv_bfloat16 h2 = __float2bfloat16(v.z*inv);
    __nv_bfloat16 h3 = __float2bfloat16(v.w*inv);
    ushort4 pk;
    pk.x = *(unsigned short*)&h0; pk.y = *(unsigned short*)&h1;
    pk.z = *(unsigned short*)&h2; pk.w = *(unsigned short*)&h3;
    *(ushort4*)(g_l2h + (size_t)row * DDIM + tid*4) = pk;
}

// ---------------- bf16 m16n8k16 MMA ------------------------------------------
__device__ __forceinline__ void mma16816(float* c, const unsigned* a, const unsigned* b)
{
    asm volatile(
        "mma.sync.aligned.m16n8k16.row.col.f32.bf16.bf16.f32 "
        "{%0,%1,%2,%3},{%4,%5,%6,%7},{%8,%9},{%0,%1,%2,%3};"
        : "+f"(c[0]), "+f"(c[1]), "+f"(c[2]), "+f"(c[3])
        : "r"(a[0]), "r"(a[1]), "r"(a[2]), "r"(a[3]), "r"(b[0]), "r"(b[1]));
}
__device__ __forceinline__ unsigned lds32(const __nv_bfloat16* p) {
    return *(const unsigned*)p;
}

// ---------------- kernel 2: fused symmetric bf16 GEMM + masked min/max -------
// Upper-triangular 128x128 tiles. 8 warps as 4 warp-rows x 2 warp-cols;
// each warp computes 32x64 via 2x8 m16n8k16 tiles. Fragments are fetched
// with direct LDS.32 (stride-40 layout is conflict-free). Row reductions via
// lc-shuffles, col reductions via lr-shuffles; smem combine, then one
// ordered-uint atomic pair per row per direction.
__global__ void __launch_bounds__(NT) k_gemm_reduce()
{
    // triangular block index -> (bi, bj), bj >= bi
    int b = blockIdx.x;
    int bi = 0, rem = b;
    while (rem >= NBLK - bi) { rem -= NBLK - bi; bi++; }
    int bj = bi + rem;

    __shared__ __align__(16) __nv_bfloat16 sA[BM*SST];   // 10240 B
    __shared__ __align__(16) __nv_bfloat16 sB[BM*SST];   // 10240 B
    __shared__ int sTi[BM], sTj[BM];

    int tid  = threadIdx.x;
    int wid  = tid >> 5;
    int lane = tid & 31;
    int wr   = wid & 3;          // warp-row: rows wr*32 .. +31
    int wc   = wid >> 2;         // warp-col: cols wc*64 .. +63
    int lr   = lane >> 2;        // 0..7
    int lc   = lane & 3;         // 0..3

    if (tid < BM) sTi[tid]      = g_tgt[bi*BM + tid];
    else          sTj[tid-BM]   = g_tgt[bj*BM + (tid-BM)];

    float acc[2][8][4];
    #pragma unroll
    for (int mt = 0; mt < 2; mt++)
        #pragma unroll
        for (int nt = 0; nt < 8; nt++)
            #pragma unroll
            for (int e = 0; e < 4; e++) acc[mt][nt][e] = 0.0f;

    const __nv_bfloat16* gA = g_l2h + (size_t)(bi*BM) * DDIM;
    const __nv_bfloat16* gB = g_l2h + (size_t)(bj*BM) * DDIM;

    // per-thread gmem->reg prefetch: 2 x uint4 (8 bf16) per tile per step
    int v0   = tid*2;
    int row0 = v0 >> 2,        seg0 = (v0 & 3);
    int row1 = (v0+1) >> 2,    seg1 = ((v0+1) & 3);

    uint4 ra0, ra1, rb0, rb1;
    {
        ra0 = *(const uint4*)(gA + (size_t)row0*DDIM + seg0*8);
        ra1 = *(const uint4*)(gA + (size_t)row1*DDIM + seg1*8);
        rb0 = *(const uint4*)(gB + (size_t)row0*DDIM + seg0*8);
        rb1 = *(const uint4*)(gB + (size_t)row1*DDIM + seg1*8);
    }

    for (int k0 = 0; k0 < DDIM; k0 += BK) {
        *(uint4*)&sA[row0*SST + seg0*8] = ra0;
        *(uint4*)&sA[row1*SST + seg1*8] = ra1;
        *(uint4*)&sB[row0*SST + seg0*8] = rb0;
        *(uint4*)&sB[row1*SST + seg1*8] = rb1;
        __syncthreads();

        if (k0 + BK < DDIM) {
            int kn = k0 + BK;
            ra0 = *(const uint4*)(gA + (size_t)row0*DDIM + kn + seg0*8);
            ra1 = *(const uint4*)(gA + (size_t)row1*DDIM + kn + seg1*8);
            rb0 = *(const uint4*)(gB + (size_t)row0*DDIM + kn + seg0*8);
            rb1 = *(const uint4*)(gB + (size_t)row1*DDIM + kn + seg1*8);
        }

        #pragma unroll
        for (int ks = 0; ks < 2; ks++) {
            int kk = ks*16 + lc*2;
            unsigned afr[2][4], bfr[8][2];
            #pragma unroll
            for (int mt = 0; mt < 2; mt++) {
                int r0 = wr*32 + mt*16 + lr;
                afr[mt][0] = lds32(&sA[r0*SST     + kk]);
                afr[mt][1] = lds32(&sA[(r0+8)*SST + kk]);
                afr[mt][2] = lds32(&sA[r0*SST     + kk + 8]);
                afr[mt][3] = lds32(&sA[(r0+8)*SST + kk + 8]);
            }
            #pragma unroll
            for (int nt = 0; nt < 8; nt++) {
                int c0 = wc*64 + nt*8 + lr;
                bfr[nt][0] = lds32(&sB[c0*SST + kk]);
                bfr[nt][1] = lds32(&sB[c0*SST + kk + 8]);
            }
            #pragma unroll
            for (int mt = 0; mt < 2; mt++)
                #pragma unroll
                for (int nt = 0; nt < 8; nt++)
                    mma16816(acc[mt][nt], afr[mt], bfr[nt]);
        }
        __syncthreads();
    }

    // reduction overlays (tiles no longer needed; all threads past last sync)
    float* rMin = (float*)sA;            // [2][128]
    float* rMax = (float*)sA + 256;      // [2][128]
    float* cMin = (float*)sB;            // [4][128]
    float* cMax = (float*)sB + 512;      // [4][128]

    // ---- row pass: each lane covers 4 rows x 16 cols; combine over lc (x1,x2)
    #pragma unroll
    for (int mt = 0; mt < 2; mt++) {
        #pragma unroll
        for (int h = 0; h < 2; h++) {
            int   r  = wr*32 + mt*16 + h*8 + lr;
            int   ti = sTi[r];
            float mn = FBIG, mx = -FBIG;
            #pragma unroll
            for (int nt = 0; nt < 8; nt++) {
                #pragma unroll
                for (int e = 0; e < 2; e++) {
                    int   c = wc*64 + nt*8 + lc*2 + e;
                    float v = acc[mt][nt][h*2 + e];
                    if (ti == sTj[c]) mn = fminf(mn, v);
                    else              mx = fmaxf(mx, v);
                }
            }
            mn = fminf(mn, __shfl_xor_sync(0xffffffffu, mn, 1));
            mn = fminf(mn, __shfl_xor_sync(0xffffffffu, mn, 2));
            mx = fmaxf(mx, __shfl_xor_sync(0xffffffffu, mx, 1));
            mx = fmaxf(mx, __shfl_xor_sync(0xffffffffu, mx, 2));
            if (lc == 0) { rMin[wc*BM + r] = mn; rMax[wc*BM + r] = mx; }
        }
    }

    // ---- col pass (symmetry; off-diagonal tiles only): combine over lr (4,8,16)
    if (bi != bj) {
        #pragma unroll
        for (int nt = 0; nt < 8; nt++) {
            #pragma unroll
            for (int e = 0; e < 2; e++) {
                int   c  = wc*64 + nt*8 + lc*2 + e;
                int   tj = sTj[c];
                float mn = FBIG, mx = -FBIG;
                #pragma unroll
                for (int mt = 0; mt < 2; mt++) {
                    #pragma unroll
                    for (int h = 0; h < 2; h++) {
                        int   r = wr*32 + mt*16 + h*8 + lr;
                        float v = acc[mt][nt][h*2 + e];
                        if (sTi[r] == tj) mn = fminf(mn, v);
                        else              mx = fmaxf(mx, v);
                    }
                }
                mn = fminf(mn, __shfl_xor_sync(0xffffffffu, mn, 4));
                mn = fminf(mn, __shfl_xor_sync(0xffffffffu, mn, 8));
                mn = fminf(mn, __shfl_xor_sync(0xffffffffu, mn, 16));
                mx = fmaxf(mx, __shfl_xor_sync(0xffffffffu, mx, 4));
                mx = fmaxf(mx, __shfl_xor_sync(0xffffffffu, mx, 8));
                mx = fmaxf(mx, __shfl_xor_sync(0xffffffffu, mx, 16));
                if (lr == 0) { cMin[wr*BM + c] = mn; cMax[wr*BM + c] = mx; }
            }
        }
    }
    __syncthreads();

    if (tid < BM) {
        float mn = fminf(rMin[tid], rMin[BM + tid]);
        float mx = fmaxf(rMax[tid], rMax[BM + tid]);
        atomicMin(&g_minpos[bi*BM + tid], ordu(mn));
        atomicMax(&g_maxneg[bi*BM + tid], ordu(mx));
        if (bi != bj) {
            float cmn = FBIG, cmx = -FBIG;
            #pragma unroll
            for (int w = 0; w < 4; w++) {
                cmn = fminf(cmn, cMin[w*BM + tid]);
                cmx = fmaxf(cmx, cMax[w*BM + tid]);
            }
            atomicMin(&g_minpos[bj*BM + tid], ordu(cmn));
            atomicMax(&g_maxneg[bj*BM + tid], ordu(cmx));
        }
    }
}

// ---------------- kernel 3: loss = mean(relu(maxneg - minpos + margin)) ------
__global__ void k_final(float* __restrict__ out)
{
    int tid = threadIdx.x;
    float s = 0.0f;
    for (int r = tid; r < NROWS; r += 256) {
        float mx = deordu(g_maxneg[r]);
        float mn = deordu(g_minpos[r]);
        s += fmaxf(mx - mn + LMARGIN, 0.0f);
    }
    __shared__ float sm[256];
    sm[tid] = s;
    __syncthreads();
    #pragma unroll
    for (int o = 128; o > 0; o >>= 1) {
        if (tid < o) sm[tid] += sm[tid + o];
        __syncthreads();
    }
    if (tid == 0) out[0] = sm[0] / (float)NROWS;
}

// ---------------- launch ------------------------------------------------------
extern "C" void kernel_launch(void* const* d_in, const int* in_sizes, int n_in,
                              void* d_out, int out_size)
{
    (void)in_sizes; (void)n_in; (void)out_size;
    const float* x   = (const float*)d_in[0];
    const int*   t32 = (const int*)d_in[1];   // int64 or int32; device-detected

    k_normalize<<<NROWS, 128>>>(x, t32);
    k_gemm_reduce<<<NTRI, NT>>>();
    k_final<<<1, 256>>>((float*)d_out);
}

// round 6
// speedup vs baseline: 1.4491x; 1.4491x over previous
#include <cuda_runtime.h>
#include <cuda_bf16.h>
#include <cstdint>

#define NROWS 8192
#define DDIM  512
#define BM    128
#define BK    32                       /* K per stage */
#define NITER (DDIM/BK)                /* 16 */
#define NBLK  (NROWS/BM)               /* 64 */
#define NTRI  (NBLK*(NBLK+1)/2)        /* 2080 */
#define STRB  80                       /* smem row stride bytes (32 bf16 + pad) */
#define TILEB (BM*STRB)                /* 10240 B per matrix per stage */
#define LMARGIN 0.5f
#define FBIG  3.402823466e+38f

// ---------------- scratch (static device globals; no allocation) -------------
__device__ __nv_bfloat16 g_l2h[NROWS*DDIM];   // normalized rows, bf16 (8 MB)
__device__ unsigned      g_minpos[NROWS];
__device__ unsigned      g_maxneg[NROWS];
__device__ int           g_tgt[NROWS];

__device__ __forceinline__ unsigned ordu(float f) {
    unsigned u = __float_as_uint(f);
    return (u & 0x80000000u) ? ~u : (u | 0x80000000u);
}
__device__ __forceinline__ float deordu(unsigned u) {
    return (u & 0x80000000u) ? __uint_as_float(u & 0x7fffffffu)
                             : __uint_as_float(~u);
}
__device__ __forceinline__ uint32_t smem_u32(const void* p) {
    uint32_t a;
    asm("{ .reg .u64 t; cvta.to.shared.u64 t, %1; cvt.u32.u64 %0, t; }"
        : "=r"(a) : "l"(p));
    return a;
}
__device__ __forceinline__ void cpasync16(uint32_t dst, const void* src) {
    asm volatile("cp.async.cg.shared.global [%0], [%1], 16;"
                 :: "r"(dst), "l"(src) : "memory");
}
__device__ __forceinline__ void cpcommit() {
    asm volatile("cp.async.commit_group;" ::: "memory");
}
template <int N>
__device__ __forceinline__ void cpwait() {
    asm volatile("cp.async.wait_group %0;" :: "n"(N) : "memory");
}
__device__ __forceinline__ void ldsm4(unsigned* r, uint32_t addr) {
    asm volatile("ldmatrix.sync.aligned.m8n8.x4.shared.b16 {%0,%1,%2,%3}, [%4];"
                 : "=r"(r[0]), "=r"(r[1]), "=r"(r[2]), "=r"(r[3]) : "r"(addr));
}
__device__ __forceinline__ void mma16816(float* c, const unsigned* a, const unsigned* b)
{
    asm volatile(
        "mma.sync.aligned.m16n8k16.row.col.f32.bf16.bf16.f32 "
        "{%0,%1,%2,%3},{%4,%5,%6,%7},{%8,%9},{%0,%1,%2,%3};"
        : "+f"(c[0]), "+f"(c[1]), "+f"(c[2]), "+f"(c[3])
        : "r"(a[0]), "r"(a[1]), "r"(a[2]), "r"(a[3]), "r"(b[0]), "r"(b[1]));
}

// ---------------- kernel 1: L2-normalize -> bf16 (warp per row) --------------
__global__ void k_normalize(const float* __restrict__ x, const int* __restrict__ t32)
{
    int tid  = threadIdx.x;
    int wid  = tid >> 5;
    int lane = tid & 31;
    int row  = blockIdx.x * 8 + wid;

    const float4* xr = (const float4*)(x + (size_t)row * DDIM);
    float4 v[4];
    #pragma unroll
    for (int i = 0; i < 4; i++) v[i] = xr[lane + 32*i];     // MLP=4
    float ss = 0.0f;
    #pragma unroll
    for (int i = 0; i < 4; i++)
        ss += v[i].x*v[i].x + v[i].y*v[i].y + v[i].z*v[i].z + v[i].w*v[i].w;
    #pragma unroll
    for (int o = 16; o > 0; o >>= 1) ss += __shfl_xor_sync(0xffffffffu, ss, o);
    float inv = rsqrtf(ss);

    // int64-vs-int32 target detection (per warp, redundant but sync-free):
    // int64 targets in [0,512) => every odd int32 word is 0.
    int hv = t32[2*lane + 1];
    unsigned bal = __ballot_sync(0xffffffffu, hv == 0);
    bool is64 = (bal == 0xffffffffu);
    if (lane == 0) {
        g_minpos[row] = ordu(FBIG);
        g_maxneg[row] = ordu(-FBIG);
        g_tgt[row]    = is64 ? t32[2*row] : t32[row];
    }

    #pragma unroll
    for (int i = 0; i < 4; i++) {
        __nv_bfloat16 h0 = __float2bfloat16(v[i].x*inv);
        __nv_bfloat16 h1 = __float2bfloat16(v[i].y*inv);
        __nv_bfloat16 h2 = __float2bfloat16(v[i].z*inv);
        __nv_bfloat16 h3 = __float2bfloat16(v[i].w*inv);
        ushort4 pk;
        pk.x = *(unsigned short*)&h0; pk.y = *(unsigned short*)&h1;
        pk.z = *(unsigned short*)&h2; pk.w = *(unsigned short*)&h3;
        *(ushort4*)(g_l2h + (size_t)row * DDIM + (lane + 32*i)*4) = pk;
    }
}

// ---------------- kernel 2: fused symmetric bf16 GEMM + masked min/max -------
// 128x128 triangular tiles, 128 threads = 4 warps (2x2), 64x64 per warp.
// cp.async double-buffered stages of K=32; ldmatrix.x4 fragment loads
// (stride-80B rows => conflict-free); m16n8k16 bf16 HMMA, fp32 acc.
__global__ void __launch_bounds__(128) k_gemm_reduce()
{
    // triangular block index -> (bi, bj), bj >= bi
    int b = blockIdx.x;
    int bi = 0, rem = b;
    while (rem >= NBLK - bi) { rem -= NBLK - bi; bi++; }
    int bj = bi + rem;

    __shared__ __align__(16) char smT[2][2][TILEB];   // [stage][A/B], 40960 B
    __shared__ int sTi[BM], sTj[BM];

    int tid  = threadIdx.x;
    int wid  = tid >> 5;
    int lane = tid & 31;
    int wr   = wid >> 1;          // warp-row: rows wr*64..+63
    int wc   = wid & 1;           // warp-col: cols wc*64..+63
    int g    = lane >> 2;         // 0..7 (mma groupID)
    int t    = lane & 3;          // 0..3

    if (tid < BM) { sTi[tid] = g_tgt[bi*BM + tid]; sTj[tid] = g_tgt[bj*BM + tid]; }

    const __nv_bfloat16* gA = g_l2h + (size_t)(bi*BM) * DDIM;
    const __nv_bfloat16* gB = g_l2h + (size_t)(bj*BM) * DDIM;

    // cp.async: 4 x 16B per thread per matrix per stage
    int ldRow[4], ldSeg[4];
    #pragma unroll
    for (int i = 0; i < 4; i++) {
        int idx = i*128 + tid;           // 16B-chunk id, 512 per matrix
        ldRow[i] = idx >> 2;             // 0..127
        ldSeg[i] = idx & 3;              // 0..3 (16B within 64B row)
    }
    auto issue_stage = [&](int c) {
        int k0 = c * BK;
        int buf = c & 1;
        uint32_t dA = smem_u32(&smT[buf][0][0]);
        uint32_t dB = smem_u32(&smT[buf][1][0]);
        #pragma unroll
        for (int i = 0; i < 4; i++) {
            unsigned off = ldRow[i]*STRB + ldSeg[i]*16;
            cpasync16(dA + off, gA + (size_t)ldRow[i]*DDIM + k0 + ldSeg[i]*8);
            cpasync16(dB + off, gB + (size_t)ldRow[i]*DDIM + k0 + ldSeg[i]*8);
        }
        cpcommit();
    };

    // ldmatrix per-lane byte offsets (within one matrix buffer)
    // A, tile mt: rows wr*64+mt*16+[0,16), k half from lane>>4
    unsigned aoff[4], boff[4];
    {
        int rsel = (lane & 7) + ((lane >> 3) & 1) * 8;
        int kby  = ((lane >> 4) & 1) * 16;
        #pragma unroll
        for (int mt = 0; mt < 4; mt++)
            aoff[mt] = (wr*64 + mt*16 + rsel)*STRB + kby;
        #pragma unroll
        for (int np = 0; np < 4; np++)
            boff[np] = (wc*64 + np*16 + rsel)*STRB + kby;
    }

    float acc[4][8][4];
    #pragma unroll
    for (int mt = 0; mt < 4; mt++)
        #pragma unroll
        for (int nt = 0; nt < 8; nt++)
            #pragma unroll
            for (int e = 0; e < 4; e++) acc[mt][nt][e] = 0.0f;

    issue_stage(0);
    issue_stage(1);

    for (int c = 0; c < NITER; c++) {
        cpwait<1>();                // stage c resident
        __syncthreads();
        int buf = c & 1;
        uint32_t bA = smem_u32(&smT[buf][0][0]);
        uint32_t bB = smem_u32(&smT[buf][1][0]);
        #pragma unroll
        for (int ks = 0; ks < 2; ks++) {
            unsigned kk = ks*32;    // 16 bf16 = 32 B
            unsigned afr[4][4], btmp[4][4];
            #pragma unroll
            for (int mt = 0; mt < 4; mt++) ldsm4(afr[mt], bA + aoff[mt] + kk);
            #pragma unroll
            for (int np = 0; np < 4; np++) ldsm4(btmp[np], bB + boff[np] + kk);
            #pragma unroll
            for (int mt = 0; mt < 4; mt++) {
                #pragma unroll
                for (int np = 0; np < 4; np++) {
                    // btmp[np] = {t0.b0, t1.b0, t0.b1, t1.b1} for n-tiles 2np,2np+1
                    unsigned b0[2] = { btmp[np][0], btmp[np][2] };
                    unsigned b1[2] = { btmp[np][1], btmp[np][3] };
                    mma16816(acc[mt][2*np],   afr[mt], b0);
                    mma16816(acc[mt][2*np+1], afr[mt], b1);
                }
            }
        }
        __syncthreads();            // all warps done reading buf
        if (c + 2 < NITER) issue_stage(c + 2);
    }

    // -------- epilogue: masked min/max (overlay reductions on dead tiles) ----
    float* rMin = (float*)&smT[0][0][0];          // [2][128]
    float* rMax = rMin + 256;
    float* cMin = rMax + 256;                     // [2][128]
    float* cMax = cMin + 256;
    bool offd = (bi != bj);

    // row pass: lane covers rows {mt*16+h*8+g}, cols {nt*8+t*2+e} of its warp
    #pragma unroll
    for (int mt = 0; mt < 4; mt++) {
        #pragma unroll
        for (int h = 0; h < 2; h++) {
            int   r  = wr*64 + mt*16 + h*8 + g;
            int   ti = sTi[r];
            float mn = FBIG, mx = -FBIG;
            #pragma unroll
            for (int nt = 0; nt < 8; nt++) {
                #pragma unroll
                for (int e = 0; e < 2; e++) {
                    float v = acc[mt][nt][h*2 + e];
                    if (ti == sTj[wc*64 + nt*8 + t*2 + e]) mn = fminf(mn, v);
                    else                                    mx = fmaxf(mx, v);
                }
            }
            mn = fminf(mn, __shfl_xor_sync(0xffffffffu, mn, 1));
            mn = fminf(mn, __shfl_xor_sync(0xffffffffu, mn, 2));
            mx = fmaxf(mx, __shfl_xor_sync(0xffffffffu, mx, 1));
            mx = fmaxf(mx, __shfl_xor_sync(0xffffffffu, mx, 2));
            if (t == 0) { rMin[wc*BM + r] = mn; rMax[wc*BM + r] = mx; }
        }
    }
    // col pass (off-diagonal only): reduce over g via shuffles 4,8,16
    if (offd) {
        #pragma unroll
        for (int nt = 0; nt < 8; nt++) {
            #pragma unroll
            for (int e = 0; e < 2; e++) {
                int   cidx = wc*64 + nt*8 + t*2 + e;
                int   tj   = sTj[cidx];
                float mn = FBIG, mx = -FBIG;
                #pragma unroll
                for (int mt = 0; mt < 4; mt++) {
                    #pragma unroll
                    for (int h = 0; h < 2; h++) {
                        float v = acc[mt][nt][h*2 + e];
                        if (sTi[wr*64 + mt*16 + h*8 + g] == tj) mn = fminf(mn, v);
                        else                                     mx = fmaxf(mx, v);
                    }
                }
                mn = fminf(mn, __shfl_xor_sync(0xffffffffu, mn, 4));
                mn = fminf(mn, __shfl_xor_sync(0xffffffffu, mn, 8));
                mn = fminf(mn, __shfl_xor_sync(0xffffffffu, mn, 16));
                mx = fmaxf(mx, __shfl_xor_sync(0xffffffffu, mx, 4));
                mx = fmaxf(mx, __shfl_xor_sync(0xffffffffu, mx, 8));
                mx = fmaxf(mx, __shfl_xor_sync(0xffffffffu, mx, 16));
                if (g == 0) { cMin[wr*BM + cidx] = mn; cMax[wr*BM + cidx] = mx; }
            }
        }
    }
    __syncthreads();

    {   // combine the two warp-halves, one atomic pair per row / per col
        float mn = fminf(rMin[tid], rMin[BM + tid]);
        float mx = fmaxf(rMax[tid], rMax[BM + tid]);
        atomicMin(&g_minpos[bi*BM + tid], ordu(mn));
        atomicMax(&g_maxneg[bi*BM + tid], ordu(mx));
        if (offd) {
            float cn = fminf(cMin[tid], cMin[BM + tid]);
            float cx = fmaxf(cMax[tid], cMax[BM + tid]);
            atomicMin(&g_minpos[bj*BM + tid], ordu(cn));
            atomicMax(&g_maxneg[bj*BM + tid], ordu(cx));
        }
    }
}

// ---------------- kernel 3: loss = mean(relu(maxneg - minpos + margin)) ------
__global__ void k_final(float* __restrict__ out)
{
    int tid = threadIdx.x;
    float s = 0.0f;
    for (int r = tid; r < NROWS; r += 256) {
        float mx = deordu(g_maxneg[r]);
        float mn = deordu(g_minpos[r]);
        s += fmaxf(mx - mn + LMARGIN, 0.0f);
    }
    __shared__ float sm[256];
    sm[tid] = s;
    __syncthreads();
    #pragma unroll
    for (int o = 128; o > 0; o >>= 1) {
        if (tid < o) sm[tid] += sm[tid + o];
        __syncthreads();
    }
    if (tid == 0) out[0] = sm[0] / (float)NROWS;
}

// ---------------- launch ------------------------------------------------------
extern "C" void kernel_launch(void* const* d_in, const int* in_sizes, int n_in,
                              void* d_out, int out_size)
{
    (void)in_sizes; (void)n_in; (void)out_size;
    const float* x   = (const float*)d_in[0];
    const int*   t32 = (const int*)d_in[1];

    k_normalize<<<NROWS/8, 256>>>(x, t32);
    k_gemm_reduce<<<NTRI, 128>>>();
    k_final<<<1, 256>>>((float*)d_out);
}

// round 7
// speedup vs baseline: 1.4668x; 1.0122x over previous
#include <cuda_runtime.h>
#include <cuda_bf16.h>
#include <cstdint>

#define NROWS 8192
#define DDIM  512
#define BM    128
#define BK    32                       /* K per stage */
#define NITER (DDIM/BK)                /* 16 */
#define NBLK  (NROWS/BM)               /* 64 */
#define NTRI  (NBLK*(NBLK+1)/2)        /* 2080 */
#define STRB  80                       /* smem row stride bytes (32 bf16 + pad) */
#define TILEB (BM*STRB)                /* 10240 B per matrix per stage */
#define STAGES 3
#define SMEM_DYN (STAGES*2*TILEB)      /* 61440 B */
#define LMARGIN 0.5f
#define FBIG  3.402823466e+38f

// ---------------- scratch (static device globals; no allocation) -------------
__device__ __nv_bfloat16 g_l2h[NROWS*DDIM];   // normalized rows, bf16 (8 MB)
__device__ unsigned      g_minpos[NROWS];
__device__ unsigned      g_maxneg[NROWS];
__device__ int           g_tgt[NROWS];

__device__ __forceinline__ unsigned ordu(float f) {
    unsigned u = __float_as_uint(f);
    return (u & 0x80000000u) ? ~u : (u | 0x80000000u);
}
__device__ __forceinline__ float deordu(unsigned u) {
    return (u & 0x80000000u) ? __uint_as_float(u & 0x7fffffffu)
                             : __uint_as_float(~u);
}
__device__ __forceinline__ uint32_t smem_u32(const void* p) {
    uint32_t a;
    asm("{ .reg .u64 t; cvta.to.shared.u64 t, %1; cvt.u32.u64 %0, t; }"
        : "=r"(a) : "l"(p));
    return a;
}
__device__ __forceinline__ void cpasync16(uint32_t dst, const void* src) {
    asm volatile("cp.async.cg.shared.global [%0], [%1], 16;"
                 :: "r"(dst), "l"(src) : "memory");
}
__device__ __forceinline__ void cpcommit() {
    asm volatile("cp.async.commit_group;" ::: "memory");
}
template <int N>
__device__ __forceinline__ void cpwait() {
    asm volatile("cp.async.wait_group %0;" :: "n"(N) : "memory");
}
__device__ __forceinline__ void ldsm4(unsigned* r, uint32_t addr) {
    asm volatile("ldmatrix.sync.aligned.m8n8.x4.shared.b16 {%0,%1,%2,%3}, [%4];"
                 : "=r"(r[0]), "=r"(r[1]), "=r"(r[2]), "=r"(r[3]) : "r"(addr));
}
__device__ __forceinline__ void mma16816(float* c, const unsigned* a, const unsigned* b)
{
    asm volatile(
        "mma.sync.aligned.m16n8k16.row.col.f32.bf16.bf16.f32 "
        "{%0,%1,%2,%3},{%4,%5,%6,%7},{%8,%9},{%0,%1,%2,%3};"
        : "+f"(c[0]), "+f"(c[1]), "+f"(c[2]), "+f"(c[3])
        : "r"(a[0]), "r"(a[1]), "r"(a[2]), "r"(a[3]), "r"(b[0]), "r"(b[1]));
}

// ---------------- kernel 1: L2-normalize -> bf16 (warp per row) --------------
__global__ void k_normalize(const float* __restrict__ x, const int* __restrict__ t32)
{
    int tid  = threadIdx.x;
    int wid  = tid >> 5;
    int lane = tid & 31;
    int row  = blockIdx.x * 8 + wid;

    const float4* xr = (const float4*)(x + (size_t)row * DDIM);
    float4 v[4];
    #pragma unroll
    for (int i = 0; i < 4; i++) v[i] = xr[lane + 32*i];
    float ss = 0.0f;
    #pragma unroll
    for (int i = 0; i < 4; i++)
        ss += v[i].x*v[i].x + v[i].y*v[i].y + v[i].z*v[i].z + v[i].w*v[i].w;
    #pragma unroll
    for (int o = 16; o > 0; o >>= 1) ss += __shfl_xor_sync(0xffffffffu, ss, o);
    float inv = rsqrtf(ss);

    // int64-vs-int32 target detection: int64 targets (<512) => odd words all 0
    int hv = t32[2*lane + 1];
    unsigned bal = __ballot_sync(0xffffffffu, hv == 0);
    bool is64 = (bal == 0xffffffffu);
    if (lane == 0) {
        g_minpos[row] = ordu(FBIG);
        g_maxneg[row] = ordu(-FBIG);
        g_tgt[row]    = is64 ? t32[2*row] : t32[row];
    }

    #pragma unroll
    for (int i = 0; i < 4; i++) {
        __nv_bfloat16 h0 = __float2bfloat16(v[i].x*inv);
        __nv_bfloat16 h1 = __float2bfloat16(v[i].y*inv);
        __nv_bfloat16 h2 = __float2bfloat16(v[i].z*inv);
        __nv_bfloat16 h3 = __float2bfloat16(v[i].w*inv);
        ushort4 pk;
        pk.x = *(unsigned short*)&h0; pk.y = *(unsigned short*)&h1;
        pk.z = *(unsigned short*)&h2; pk.w = *(unsigned short*)&h3;
        *(ushort4*)(g_l2h + (size_t)row * DDIM + (lane + 32*i)*4) = pk;
    }
}

// ---------------- kernel 2: fused symmetric bf16 GEMM + masked min/max -------
// 128x128 triangular tiles, 256 threads = 8 warps (4 wr x 2 wc), 32x64/warp.
// 3-stage cp.async pipeline, ONE __syncthreads per k-iter. ldmatrix.x4 frags
// (stride-80B rows, conflict-free); m16n8k16 bf16 HMMA, fp32 acc.
__global__ void __launch_bounds__(256, 2) k_gemm_reduce()
{
    extern __shared__ __align__(16) char dsm[];

    // triangular block index -> (bi, bj), bj >= bi
    int b = blockIdx.x;
    int bi = 0, rem = b;
    while (rem >= NBLK - bi) { rem -= NBLK - bi; bi++; }
    int bj = bi + rem;

    __shared__ int sTi[BM], sTj[BM];

    int tid  = threadIdx.x;
    int wid  = tid >> 5;
    int lane = tid & 31;
    int wr   = wid >> 1;          // 0..3 : rows wr*32..+31
    int wc   = wid & 1;           // 0..1 : cols wc*64..+63
    int g    = lane >> 2;         // 0..7
    int t    = lane & 3;          // 0..3

    if (tid < BM) { sTi[tid] = g_tgt[bi*BM + tid]; sTj[tid] = g_tgt[bj*BM + tid]; }

    const __nv_bfloat16* gA = g_l2h + (size_t)(bi*BM) * DDIM;
    const __nv_bfloat16* gB = g_l2h + (size_t)(bj*BM) * DDIM;
    uint32_t dsmBase = smem_u32(dsm);

    // cp.async: 2 x 16B per thread per matrix per stage (512 chunks/matrix)
    int ldRow[2], ldSeg[2];
    #pragma unroll
    for (int i = 0; i < 2; i++) {
        int idx = i*256 + tid;
        ldRow[i] = idx >> 2;
        ldSeg[i] = idx & 3;
    }
    auto issue_stage = [&](int c) {
        int k0 = c * BK;
        uint32_t dA = dsmBase + (unsigned)(c % STAGES) * (2*TILEB);
        uint32_t dB = dA + TILEB;
        #pragma unroll
        for (int i = 0; i < 2; i++) {
            unsigned off = ldRow[i]*STRB + ldSeg[i]*16;
            cpasync16(dA + off, gA + (size_t)ldRow[i]*DDIM + k0 + ldSeg[i]*8);
            cpasync16(dB + off, gB + (size_t)ldRow[i]*DDIM + k0 + ldSeg[i]*8);
        }
        cpcommit();
    };

    // ldmatrix per-lane byte offsets (validated layout from R5)
    unsigned aoff[2], boff[4];
    {
        int rsel = lane & 15;
        int kby  = ((lane >> 4) & 1) * 16;
        #pragma unroll
        for (int mt = 0; mt < 2; mt++)
            aoff[mt] = (wr*32 + mt*16 + rsel)*STRB + kby;
        #pragma unroll
        for (int np = 0; np < 4; np++)
            boff[np] = (wc*64 + np*16 + rsel)*STRB + kby;
    }

    float acc[2][8][4];
    #pragma unroll
    for (int mt = 0; mt < 2; mt++)
        #pragma unroll
        for (int nt = 0; nt < 8; nt++)
            #pragma unroll
            for (int e = 0; e < 4; e++) acc[mt][nt][e] = 0.0f;

    issue_stage(0);
    issue_stage(1);

    for (int c = 0; c < NITER; c++) {
        cpwait<1>();                 // stage c resident
        __syncthreads();             // fences iter c-1 reads of buf (c-1)%3
        if (c + 2 < NITER) issue_stage(c + 2);   // writes buf (c-1)%3 : safe
        else cpcommit();                         // keep group count in step

        uint32_t bA = dsmBase + (unsigned)(c % STAGES) * (2*TILEB);
        uint32_t bB = bA + TILEB;
        #pragma unroll
        for (int ks = 0; ks < 2; ks++) {
            unsigned kk = ks*32;
            unsigned afr[2][4], btmp[4][4];
            #pragma unroll
            for (int mt = 0; mt < 2; mt++) ldsm4(afr[mt], bA + aoff[mt] + kk);
            #pragma unroll
            for (int np = 0; np < 4; np++) ldsm4(btmp[np], bB + boff[np] + kk);
            #pragma unroll
            for (int mt = 0; mt < 2; mt++) {
                #pragma unroll
                for (int np = 0; np < 4; np++) {
                    unsigned b0[2] = { btmp[np][0], btmp[np][2] };
                    unsigned b1[2] = { btmp[np][1], btmp[np][3] };
                    mma16816(acc[mt][2*np],   afr[mt], b0);
                    mma16816(acc[mt][2*np+1], afr[mt], b1);
                }
            }
        }
    }
    __syncthreads();   // all compute done; overlay reductions on stage smem

    // -------- epilogue: masked min/max --------
    float* rMin = (float*)dsm;            // [2][128]
    float* rMax = rMin + 256;
    float* cMin = rMax + 256;             // [4][128]
    float* cMax = cMin + 512;
    bool offd = (bi != bj);

    // row pass: reduce over t via shuffles 1,2
    #pragma unroll
    for (int mt = 0; mt < 2; mt++) {
        #pragma unroll
        for (int h = 0; h < 2; h++) {
            int   r  = wr*32 + mt*16 + h*8 + g;
            int   ti = sTi[r];
            float mn = FBIG, mx = -FBIG;
            #pragma unroll
            for (int nt = 0; nt < 8; nt++) {
                #pragma unroll
                for (int e = 0; e < 2; e++) {
                    float v = acc[mt][nt][h*2 + e];
                    if (ti == sTj[wc*64 + nt*8 + t*2 + e]) mn = fminf(mn, v);
                    else                                    mx = fmaxf(mx, v);
                }
            }
            mn = fminf(mn, __shfl_xor_sync(0xffffffffu, mn, 1));
            mn = fminf(mn, __shfl_xor_sync(0xffffffffu, mn, 2));
            mx = fmaxf(mx, __shfl_xor_sync(0xffffffffu, mx, 1));
            mx = fmaxf(mx, __shfl_xor_sync(0xffffffffu, mx, 2));
            if (t == 0) { rMin[wc*BM + r] = mn; rMax[wc*BM + r] = mx; }
        }
    }
    // col pass: reduce over g via shuffles 4,8,16 (off-diagonal only)
    if (offd) {
        #pragma unroll
        for (int nt = 0; nt < 8; nt++) {
            #pragma unroll
            for (int e = 0; e < 2; e++) {
                int   cidx = wc*64 + nt*8 + t*2 + e;
                int   tj   = sTj[cidx];
                float mn = FBIG, mx = -FBIG;
                #pragma unroll
                for (int mt = 0; mt < 2; mt++) {
                    #pragma unroll
                    for (int h = 0; h < 2; h++) {
                        float v = acc[mt][nt][h*2 + e];
                        if (sTi[wr*32 + mt*16 + h*8 + g] == tj) mn = fminf(mn, v);
                        else                                     mx = fmaxf(mx, v);
                    }
                }
                mn = fminf(mn, __shfl_xor_sync(0xffffffffu, mn, 4));
                mn = fminf(mn, __shfl_xor_sync(0xffffffffu, mn, 8));
                mn = fminf(mn, __shfl_xor_sync(0xffffffffu, mn, 16));
                mx = fmaxf(mx, __shfl_xor_sync(0xffffffffu, mx, 4));
                mx = fmaxf(mx, __shfl_xor_sync(0xffffffffu, mx, 8));
                mx = fmaxf(mx, __shfl_xor_sync(0xffffffffu, mx, 16));
                if (g == 0) { cMin[wr*BM + cidx] = mn; cMax[wr*BM + cidx] = mx; }
            }
        }
    }
    __syncthreads();

    if (tid < BM) {          // row results -> bi rows
        float mn = fminf(rMin[tid], rMin[BM + tid]);
        float mx = fmaxf(rMax[tid], rMax[BM + tid]);
        atomicMin(&g_minpos[bi*BM + tid], ordu(mn));
        atomicMax(&g_maxneg[bi*BM + tid], ordu(mx));
    } else if (offd) {       // col results -> bj rows
        int cc = tid - BM;
        float mn = FBIG, mx = -FBIG;
        #pragma unroll
        for (int w = 0; w < 4; w++) {
            mn = fminf(mn, cMin[w*BM + cc]);
            mx = fmaxf(mx, cMax[w*BM + cc]);
        }
        atomicMin(&g_minpos[bj*BM + cc], ordu(mn));
        atomicMax(&g_maxneg[bj*BM + cc], ordu(mx));
    }
}

// ---------------- kernel 3: loss = mean(relu(maxneg - minpos + margin)) ------
__global__ void k_final(float* __restrict__ out)
{
    int tid = threadIdx.x;
    float s = 0.0f;
    #pragma unroll
    for (int i = 0; i < NROWS/1024; i++) {
        int r = tid + i*1024;
        float mx = deordu(g_maxneg[r]);
        float mn = deordu(g_minpos[r]);
        s += fmaxf(mx - mn + LMARGIN, 0.0f);
    }
    __shared__ float sm[1024];
    sm[tid] = s;
    __syncthreads();
    #pragma unroll
    for (int o = 512; o > 0; o >>= 1) {
        if (tid < o) sm[tid] += sm[tid + o];
        __syncthreads();
    }
    if (tid == 0) out[0] = sm[0] / (float)NROWS;
}

// ---------------- launch ------------------------------------------------------
extern "C" void kernel_launch(void* const* d_in, const int* in_sizes, int n_in,
                              void* d_out, int out_size)
{
    (void)in_sizes; (void)n_in; (void)out_size;
    const float* x   = (const float*)d_in[0];
    const int*   t32 = (const int*)d_in[1];

    cudaFuncSetAttribute(k_gemm_reduce,
                         cudaFuncAttributeMaxDynamicSharedMemorySize, SMEM_DYN);
    k_normalize<<<NROWS/8, 256>>>(x, t32);
    k_gemm_reduce<<<NTRI, 256, SMEM_DYN>>>();
    k_final<<<1, 1024>>>((float*)d_out);
}

// round 8
// speedup vs baseline: 2.3600x; 1.6090x over previous
#include <cuda_runtime.h>
#include <cuda_bf16.h>
#include <cstdint>

#define NROWS 8192
#define DDIM  512
#define BM    128
#define BK    64                       /* K (int8 elems) per stage */
#define NITER (DDIM/BK)                /* 8 */
#define NBLK  (NROWS/BM)               /* 64 */
#define NTRI  (NBLK*(NBLK+1)/2)        /* 2080 */
#define STRB  80                       /* smem row stride bytes (64 int8 + pad) */
#define TILEB (BM*STRB)                /* 10240 B per matrix per stage */
#define STAGES 3
#define SMEM_DYN (STAGES*2*TILEB)      /* 61440 B */
#define LMARGIN 0.5f
#define FBIG  3.402823466e+38f

// ---------------- scratch (static device globals; no allocation) -------------
__device__ int8_t   g_q8[NROWS*DDIM];     // quantized normalized rows (4 MB)
__device__ float    g_scl[NROWS];         // per-row dequant scale
__device__ unsigned g_minpos[NROWS];
__device__ unsigned g_maxneg[NROWS];
__device__ int      g_tgt[NROWS];

__device__ __forceinline__ unsigned ordu(float f) {
    unsigned u = __float_as_uint(f);
    return (u & 0x80000000u) ? ~u : (u | 0x80000000u);
}
__device__ __forceinline__ float deordu(unsigned u) {
    return (u & 0x80000000u) ? __uint_as_float(u & 0x7fffffffu)
                             : __uint_as_float(~u);
}
__device__ __forceinline__ uint32_t smem_u32(const void* p) {
    uint32_t a;
    asm("{ .reg .u64 t; cvta.to.shared.u64 t, %1; cvt.u32.u64 %0, t; }"
        : "=r"(a) : "l"(p));
    return a;
}
__device__ __forceinline__ void cpasync16(uint32_t dst, const void* src) {
    asm volatile("cp.async.cg.shared.global [%0], [%1], 16;"
                 :: "r"(dst), "l"(src) : "memory");
}
__device__ __forceinline__ void cpcommit() {
    asm volatile("cp.async.commit_group;" ::: "memory");
}
template <int N>
__device__ __forceinline__ void cpwait() {
    asm volatile("cp.async.wait_group %0;" :: "n"(N) : "memory");
}
__device__ __forceinline__ void ldsm4(unsigned* r, uint32_t addr) {
    asm volatile("ldmatrix.sync.aligned.m8n8.x4.shared.b16 {%0,%1,%2,%3}, [%4];"
                 : "=r"(r[0]), "=r"(r[1]), "=r"(r[2]), "=r"(r[3]) : "r"(addr));
}
// int8 MMA: m16n8k32, s32 accumulate
__device__ __forceinline__ void mma_s8(int* c, const unsigned* a, const unsigned* b)
{
    asm volatile(
        "mma.sync.aligned.m16n8k32.row.col.s32.s8.s8.s32 "
        "{%0,%1,%2,%3},{%4,%5,%6,%7},{%8,%9},{%0,%1,%2,%3};"
        : "+r"(c[0]), "+r"(c[1]), "+r"(c[2]), "+r"(c[3])
        : "r"(a[0]), "r"(a[1]), "r"(a[2]), "r"(a[3]), "r"(b[0]), "r"(b[1]));
}

// -------- kernel 1: L2-normalize -> per-row int8 quant (warp per row) --------
__global__ void k_normalize(const float* __restrict__ x, const int* __restrict__ t32)
{
    int tid  = threadIdx.x;
    int wid  = tid >> 5;
    int lane = tid & 31;
    int row  = blockIdx.x * 8 + wid;

    const float4* xr = (const float4*)(x + (size_t)row * DDIM);
    float4 v[4];
    #pragma unroll
    for (int i = 0; i < 4; i++) v[i] = xr[lane + 32*i];
    float ss = 0.0f, ma = 0.0f;
    #pragma unroll
    for (int i = 0; i < 4; i++) {
        ss += v[i].x*v[i].x + v[i].y*v[i].y + v[i].z*v[i].z + v[i].w*v[i].w;
        ma = fmaxf(ma, fmaxf(fmaxf(fabsf(v[i].x), fabsf(v[i].y)),
                             fmaxf(fabsf(v[i].z), fabsf(v[i].w))));
    }
    #pragma unroll
    for (int o = 16; o > 0; o >>= 1) {
        ss += __shfl_xor_sync(0xffffffffu, ss, o);
        ma  = fmaxf(ma, __shfl_xor_sync(0xffffffffu, ma, o));
    }
    float inv = rsqrtf(ss);
    float qs  = 127.0f / ma;            // raw -> int8
    float scl = ma * inv * (1.0f/127.0f); // int8 -> normalized float

    // int64-vs-int32 target detection: int64 targets (<512) => odd words all 0
    int hv = t32[2*lane + 1];
    unsigned bal = __ballot_sync(0xffffffffu, hv == 0);
    bool is64 = (bal == 0xffffffffu);
    if (lane == 0) {
        g_minpos[row] = ordu(FBIG);
        g_maxneg[row] = ordu(-FBIG);
        g_tgt[row]    = is64 ? t32[2*row] : t32[row];
        g_scl[row]    = scl;
    }

    #pragma unroll
    for (int i = 0; i < 4; i++) {
        int q0 = __float2int_rn(v[i].x * qs);
        int q1 = __float2int_rn(v[i].y * qs);
        int q2 = __float2int_rn(v[i].z * qs);
        int q3 = __float2int_rn(v[i].w * qs);
        unsigned pk = (unsigned)(q0 & 0xff) | ((unsigned)(q1 & 0xff) << 8) |
                      ((unsigned)(q2 & 0xff) << 16) | ((unsigned)(q3 & 0xff) << 24);
        *(unsigned*)(g_q8 + (size_t)row * DDIM + (lane + 32*i)*4) = pk;
    }
}

// ---------------- kernel 2: fused symmetric int8 GEMM + masked min/max ------
// 128x128 triangular tiles, 256 threads = 8 warps (4 wr x 2 wc), 32x64/warp.
// 3-stage cp.async pipeline; ldmatrix.x4 frags (stride-80B, conflict-free);
// m16n8k32 s8 IMMA, s32 acc; dequant in epilogue via per-row scales.
__global__ void __launch_bounds__(256, 2) k_gemm_reduce()
{
    extern __shared__ __align__(16) char dsm[];

    // triangular block index -> (bi, bj), bj >= bi
    int b = blockIdx.x;
    int bi = 0, rem = b;
    while (rem >= NBLK - bi) { rem -= NBLK - bi; bi++; }
    int bj = bi + rem;

    __shared__ int   sTi[BM], sTj[BM];
    __shared__ float sSa[BM], sSb[BM];

    int tid  = threadIdx.x;
    int wid  = tid >> 5;
    int lane = tid & 31;
    int wr   = wid >> 1;          // 0..3 : rows wr*32..+31
    int wc   = wid & 1;           // 0..1 : cols wc*64..+63
    int g    = lane >> 2;         // 0..7
    int t    = lane & 3;          // 0..3

    if (tid < BM) { sTi[tid] = g_tgt[bi*BM + tid]; sSa[tid] = g_scl[bi*BM + tid]; }
    else { int c2 = tid - BM; sTj[c2] = g_tgt[bj*BM + c2]; sSb[c2] = g_scl[bj*BM + c2]; }

    const int8_t* gA = g_q8 + (size_t)(bi*BM) * DDIM;
    const int8_t* gB = g_q8 + (size_t)(bj*BM) * DDIM;
    uint32_t dsmBase = smem_u32(dsm);

    // cp.async: 2 x 16B per thread per matrix per stage (512 chunks/matrix)
    int ldRow[2], ldSeg[2];
    #pragma unroll
    for (int i = 0; i < 2; i++) {
        int idx = i*256 + tid;
        ldRow[i] = idx >> 2;
        ldSeg[i] = idx & 3;
    }
    auto issue_stage = [&](int c) {
        int k0 = c * BK;
        uint32_t dA = dsmBase + (unsigned)(c % STAGES) * (2*TILEB);
        uint32_t dB = dA + TILEB;
        #pragma unroll
        for (int i = 0; i < 2; i++) {
            unsigned off = ldRow[i]*STRB + ldSeg[i]*16;
            cpasync16(dA + off, gA + (size_t)ldRow[i]*DDIM + k0 + ldSeg[i]*16);
            cpasync16(dB + off, gB + (size_t)ldRow[i]*DDIM + k0 + ldSeg[i]*16);
        }
        cpcommit();
    };

    // ldmatrix per-lane byte offsets (same addressing as validated bf16 path)
    unsigned aoff[2], boff[4];
    {
        int rsel = lane & 15;
        int kby  = ((lane >> 4) & 1) * 16;
        #pragma unroll
        for (int mt = 0; mt < 2; mt++)
            aoff[mt] = (wr*32 + mt*16 + rsel)*STRB + kby;
        #pragma unroll
        for (int np = 0; np < 4; np++)
            boff[np] = (wc*64 + np*16 + rsel)*STRB + kby;
    }

    int acc[2][8][4];
    #pragma unroll
    for (int mt = 0; mt < 2; mt++)
        #pragma unroll
        for (int nt = 0; nt < 8; nt++)
            #pragma unroll
            for (int e = 0; e < 4; e++) acc[mt][nt][e] = 0;

    issue_stage(0);
    issue_stage(1);

    for (int c = 0; c < NITER; c++) {
        cpwait<1>();                 // stage c resident
        __syncthreads();             // fences iter c-1 reads of buf (c-1)%3
        if (c + 2 < NITER) issue_stage(c + 2);
        else cpcommit();             // keep group count in step

        uint32_t bA = dsmBase + (unsigned)(c % STAGES) * (2*TILEB);
        uint32_t bB = bA + TILEB;
        #pragma unroll
        for (int ks = 0; ks < 2; ks++) {
            unsigned kk = ks*32;     // 32 int8 = 32 B per k32 step
            unsigned afr[2][4], btmp[4][4];
            #pragma unroll
            for (int mt = 0; mt < 2; mt++) ldsm4(afr[mt], bA + aoff[mt] + kk);
            #pragma unroll
            for (int np = 0; np < 4; np++) ldsm4(btmp[np], bB + boff[np] + kk);
            #pragma unroll
            for (int mt = 0; mt < 2; mt++) {
                #pragma unroll
                for (int np = 0; np < 4; np++) {
                    unsigned b0[2] = { btmp[np][0], btmp[np][2] };
                    unsigned b1[2] = { btmp[np][1], btmp[np][3] };
                    mma_s8(acc[mt][2*np],   afr[mt], b0);
                    mma_s8(acc[mt][2*np+1], afr[mt], b1);
                }
            }
        }
    }
    __syncthreads();   // compute done; overlay reductions on stage smem

    // -------- epilogue: dequant + masked min/max --------
    float* rMin = (float*)dsm;            // [2][128]
    float* rMax = rMin + 256;
    float* cMin = rMax + 256;             // [4][128]
    float* cMax = cMin + 512;
    bool offd = (bi != bj);

    // row pass: reduce over t via shuffles 1,2
    #pragma unroll
    for (int mt = 0; mt < 2; mt++) {
        #pragma unroll
        for (int h = 0; h < 2; h++) {
            int   r  = wr*32 + mt*16 + h*8 + g;
            int   ti = sTi[r];
            float sa = sSa[r];
            float mn = FBIG, mx = -FBIG;
            #pragma unroll
            for (int nt = 0; nt < 8; nt++) {
                #pragma unroll
                for (int e = 0; e < 2; e++) {
                    int   cidx = wc*64 + nt*8 + t*2 + e;
                    float v = (float)acc[mt][nt][h*2 + e] * sa * sSb[cidx];
                    if (ti == sTj[cidx]) mn = fminf(mn, v);
                    else                 mx = fmaxf(mx, v);
                }
            }
            mn = fminf(mn, __shfl_xor_sync(0xffffffffu, mn, 1));
            mn = fminf(mn, __shfl_xor_sync(0xffffffffu, mn, 2));
            mx = fmaxf(mx, __shfl_xor_sync(0xffffffffu, mx, 1));
            mx = fmaxf(mx, __shfl_xor_sync(0xffffffffu, mx, 2));
            if (t == 0) { rMin[wc*BM + r] = mn; rMax[wc*BM + r] = mx; }
        }
    }
    // col pass: reduce over g via shuffles 4,8,16 (off-diagonal only)
    if (offd) {
        #pragma unroll
        for (int nt = 0; nt < 8; nt++) {
            #pragma unroll
            for (int e = 0; e < 2; e++) {
                int   cidx = wc*64 + nt*8 + t*2 + e;
                int   tj   = sTj[cidx];
                float sb   = sSb[cidx];
                float mn = FBIG, mx = -FBIG;
                #pragma unroll
                for (int mt = 0; mt < 2; mt++) {
                    #pragma unroll
                    for (int h = 0; h < 2; h++) {
                        int   r = wr*32 + mt*16 + h*8 + g;
                        float v = (float)acc[mt][nt][h*2 + e] * sSa[r] * sb;
                        if (sTi[r] == tj) mn = fminf(mn, v);
                        else              mx = fmaxf(mx, v);
                    }
                }
                mn = fminf(mn, __shfl_xor_sync(0xffffffffu, mn, 4));
                mn = fminf(mn, __shfl_xor_sync(0xffffffffu, mn, 8));
                mn = fminf(mn, __shfl_xor_sync(0xffffffffu, mn, 16));
                mx = fmaxf(mx, __shfl_xor_sync(0xffffffffu, mx, 4));
                mx = fmaxf(mx, __shfl_xor_sync(0xffffffffu, mx, 8));
                mx = fmaxf(mx, __shfl_xor_sync(0xffffffffu, mx, 16));
                if (g == 0) { cMin[wr*BM + cidx] = mn; cMax[wr*BM + cidx] = mx; }
            }
        }
    }
    __syncthreads();

    if (tid < BM) {          // row results -> bi rows
        float mn = fminf(rMin[tid], rMin[BM + tid]);
        float mx = fmaxf(rMax[tid], rMax[BM + tid]);
        atomicMin(&g_minpos[bi*BM + tid], ordu(mn));
        atomicMax(&g_maxneg[bi*BM + tid], ordu(mx));
    } else if (offd) {       // col results -> bj rows
        int cc = tid - BM;
        float mn = FBIG, mx = -FBIG;
        #pragma unroll
        for (int w = 0; w < 4; w++) {
            mn = fminf(mn, cMin[w*BM + cc]);
            mx = fmaxf(mx, cMax[w*BM + cc]);
        }
        atomicMin(&g_minpos[bj*BM + cc], ordu(mn));
        atomicMax(&g_maxneg[bj*BM + cc], ordu(mx));
    }
}

// ---------------- kernel 3: loss = mean(relu(maxneg - minpos + margin)) ------
__global__ void k_final(float* __restrict__ out)
{
    int tid = threadIdx.x;
    float s = 0.0f;
    #pragma unroll
    for (int i = 0; i < NROWS/1024; i++) {
        int r = tid + i*1024;
        float mx = deordu(g_maxneg[r]);
        float mn = deordu(g_minpos[r]);
        s += fmaxf(mx - mn + LMARGIN, 0.0f);
    }
    __shared__ float sm[1024];
    sm[tid] = s;
    __syncthreads();
    #pragma unroll
    for (int o = 512; o > 0; o >>= 1) {
        if (tid < o) sm[tid] += sm[tid + o];
        __syncthreads();
    }
    if (tid == 0) out[0] = sm[0] / (float)NROWS;
}

// ---------------- launch ------------------------------------------------------
extern "C" void kernel_launch(void* const* d_in, const int* in_sizes, int n_in,
                              void* d_out, int out_size)
{
    (void)in_sizes; (void)n_in; (void)out_size;
    const float* x   = (const float*)d_in[0];
    const int*   t32 = (const int*)d_in[1];

    cudaFuncSetAttribute(k_gemm_reduce,
                         cudaFuncAttributeMaxDynamicSharedMemorySize, SMEM_DYN);
    k_normalize<<<NROWS/8, 256>>>(x, t32);
    k_gemm_reduce<<<NTRI, 256, SMEM_DYN>>>();
    k_final<<<1, 1024>>>((float*)d_out);
}